// round 5
// baseline (speedup 1.0000x reference)
#include <cuda_runtime.h>
#include <cuda_bf16.h>
#include <cstdint>

// Problem constants
#define KCODES 16384
#define DDIM   2048
#define NTOK   8192
#define BB 8
#define CCH 2048
#define HH 32
#define WW 32

// Candidate / GEMM config
#define CAP    256
#define KPARTS 8
#define BM 128
#define BN 128
#define BK 32
#define SROWB 40            // padded smem row: 32 + 8 elems = 80B; conflict-free for ldmatrix
#define NSTAGE (DDIM / BK)  // 64 k-stages
#define MARGIN 3e-3f

// ---------------- scratch (device globals: no allocations allowed) ----------------
__device__ float          g_Ef32[(size_t)KCODES * DDIM];   // normalized embedding fp32
__device__ __nv_bfloat16  g_Ebf16[(size_t)KCODES * DDIM];  // normalized embedding bf16
__device__ float          g_Zf32[(size_t)NTOK * DDIM];     // normalized tokens fp32
__device__ __nv_bfloat16  g_Zbf16[(size_t)NTOK * DDIM];    // normalized tokens bf16
__device__ int            g_tokmax[NTOK];                  // ordered-int global bf16 max per token
__device__ int            g_cand_cnt[NTOK];
__device__ int            g_cand_code[NTOK * CAP];
__device__ float          g_cand_val[NTOK * CAP];
__device__ int            g_idx[NTOK];

// monotone float<->int ordering (handles negatives)
__device__ __forceinline__ int f2ord(float f) {
    int i = __float_as_int(f);
    return (i >= 0) ? i : (i ^ 0x7fffffff);
}
__device__ __forceinline__ float ord2f(int i) {
    return __int_as_float((i >= 0) ? i : (i ^ 0x7fffffff));
}

__device__ __forceinline__ uint32_t smem_u32(const void* p) {
    return (uint32_t)__cvta_generic_to_shared(p);
}
__device__ __forceinline__ void ldm4(uint32_t r[4], uint32_t a) {
    asm volatile("ldmatrix.sync.aligned.m8n8.x4.shared.b16 {%0,%1,%2,%3}, [%4];"
                 : "=r"(r[0]), "=r"(r[1]), "=r"(r[2]), "=r"(r[3]) : "r"(a));
}
__device__ __forceinline__ void mma16816(float c[4], const uint32_t a[4], uint32_t b0, uint32_t b1) {
    asm volatile(
        "mma.sync.aligned.m16n8k16.row.col.f32.bf16.bf16.f32 "
        "{%0,%1,%2,%3},{%4,%5,%6,%7},{%8,%9},{%0,%1,%2,%3};"
        : "+f"(c[0]), "+f"(c[1]), "+f"(c[2]), "+f"(c[3])
        : "r"(a[0]), "r"(a[1]), "r"(a[2]), "r"(a[3]), "r"(b0), "r"(b1));
}
__device__ __forceinline__ void cpasync16(uint32_t saddr, const void* gaddr) {
    asm volatile("cp.async.cg.shared.global [%0], [%1], 16;" :: "r"(saddr), "l"(gaddr));
}
__device__ __forceinline__ void cp_commit() {
    asm volatile("cp.async.commit_group;");
}
template <int N>
__device__ __forceinline__ void cp_wait() {
    asm volatile("cp.async.wait_group %0;" :: "n"(N));
}

// ---------------- init per-launch state ----------------
__global__ void k_init() {
    int i = blockIdx.x * blockDim.x + threadIdx.x;
    if (i < NTOK) {
        g_cand_cnt[i] = 0;
        g_tokmax[i]  = 0x80000000;  // INT_MIN <= all ordered values
    }
}

// ---------------- normalize embedding rows ----------------
__global__ void k_norm_embed(const float* __restrict__ emb) {
    int r = blockIdx.x;
    int tid = threadIdx.x;
    __shared__ float red[256];
    __shared__ float s_scale;
    const float4* src = (const float4*)(emb + (size_t)r * DDIM);
    float4 v0 = src[tid * 2 + 0];
    float4 v1 = src[tid * 2 + 1];
    float s = v0.x*v0.x + v0.y*v0.y + v0.z*v0.z + v0.w*v0.w
            + v1.x*v1.x + v1.y*v1.y + v1.z*v1.z + v1.w*v1.w;
    red[tid] = s;
    __syncthreads();
    for (int off = 128; off > 0; off >>= 1) {
        if (tid < off) red[tid] += red[tid + off];
        __syncthreads();
    }
    if (tid == 0) s_scale = 1.0f / fmaxf(sqrtf(red[0]), 1e-12f);
    __syncthreads();
    float sc = s_scale;
    float4 o0 = make_float4(v0.x*sc, v0.y*sc, v0.z*sc, v0.w*sc);
    float4 o1 = make_float4(v1.x*sc, v1.y*sc, v1.z*sc, v1.w*sc);
    ((float4*)(g_Ef32 + (size_t)r * DDIM))[tid * 2 + 0] = o0;
    ((float4*)(g_Ef32 + (size_t)r * DDIM))[tid * 2 + 1] = o1;
    __nv_bfloat16* db = g_Ebf16 + (size_t)r * DDIM + tid * 8;
    db[0] = __float2bfloat16_rn(o0.x); db[1] = __float2bfloat16_rn(o0.y);
    db[2] = __float2bfloat16_rn(o0.z); db[3] = __float2bfloat16_rn(o0.w);
    db[4] = __float2bfloat16_rn(o1.x); db[5] = __float2bfloat16_rn(o1.y);
    db[6] = __float2bfloat16_rn(o1.z); db[7] = __float2bfloat16_rn(o1.w);
}

// ---------------- transpose+normalize tokens: (B,C,H,W) -> [N,D] ----------------
__global__ void k_prep(const float* __restrict__ hid) {
    int bh = blockIdx.x;            // b*32 + h
    int b = bh >> 5, h = bh & 31;
    int n0 = bh * 32;               // token base: n = (b*H+h)*W + w
    int tid = threadIdx.x;
    int w = tid & 31, j = tid >> 5; // j in 0..7
    __shared__ float red[8][32];
    __shared__ float invn[32];
    __shared__ float st[64][33];

    float ss = 0.0f;
    for (int c = j; c < DDIM; c += 8) {
        float v = hid[(((size_t)b * CCH + c) * HH + h) * WW + w];
        ss += v * v;
    }
    red[j][w] = ss;
    __syncthreads();
    if (tid < 32) {
        float t = 0.0f;
        #pragma unroll
        for (int jj = 0; jj < 8; jj++) t += red[jj][tid];
        invn[tid] = 1.0f / fmaxf(sqrtf(t), 1e-12f);
    }
    __syncthreads();

    for (int cb = 0; cb < DDIM; cb += 64) {
        float sc = invn[w];
        for (int r = j; r < 64; r += 8)
            st[r][w] = hid[(((size_t)b * CCH + cb + r) * HH + h) * WW + w] * sc;
        __syncthreads();
        int tok = tid >> 3, cc = tid & 7;
        size_t base = (size_t)(n0 + tok) * DDIM + cb;
        #pragma unroll
        for (int kk = 0; kk < 8; kk++) {
            int c = cc * 8 + kk;
            float v = st[c][tok];
            g_Zf32[base + c] = v;
            g_Zbf16[base + c] = __float2bfloat16_rn(v);
        }
        __syncthreads();
    }
}

// ---------------- bf16 GEMM (cp.async double-buffered) + candidate tracking ----------------
__global__ void __launch_bounds__(256, 2) k_gemm() {
    __shared__ __align__(16) __nv_bfloat16 sZ[2][BM][SROWB];
    __shared__ __align__(16) __nv_bfloat16 sE[2][BN][SROWB];
    __shared__ int smax[BM];

    int tid = threadIdx.x;
    int lane = tid & 31;
    int warp = tid >> 5;
    int wm = warp >> 1;     // 0..3, 32 rows each
    int wn = warp & 1;      // 0..1, 64 cols each

    int mtile = blockIdx.x;
    int kpart = blockIdx.y;
    int tokenbase = mtile * BM;
    int codebase0 = kpart * (KCODES / KPARTS);

    if (tid < BM) smax[tid] = 0x80000000;
    __syncthreads();

    // per-thread cp.async assignment: 2 chunks of 16B per matrix per stage
    // chunk = tid*2 + i; row = chunk>>2; col = (chunk&3)*8 elems
    int ld_row0 = (tid * 2 + 0) >> 2, ld_co0 = ((tid * 2 + 0) & 3) * 8;
    int ld_row1 = (tid * 2 + 1) >> 2, ld_co1 = ((tid * 2 + 1) & 3) * 8;

    // per-lane invariant smem read offsets (in elements)
    int a_row_off = (lane & 15);
    int a_col_off = (lane >> 4) * 8;
    int b_row_off = (lane & 7) + ((lane >> 4) << 3);
    int b_col_off = ((lane >> 3) & 1) << 3;

    const int NT = (KCODES / KPARTS) / BN;  // 16 code tiles per block
    for (int ct = 0; ct < NT; ct++) {
        int codebase = codebase0 + ct * BN;
        float acc[2][8][4];
        #pragma unroll
        for (int a = 0; a < 2; a++)
            #pragma unroll
            for (int bfn = 0; bfn < 8; bfn++)
                #pragma unroll
                for (int q = 0; q < 4; q++) acc[a][bfn][q] = 0.0f;

        // issue stage 0
        {
            cpasync16(smem_u32(&sZ[0][ld_row0][ld_co0]),
                      g_Zbf16 + (size_t)(tokenbase + ld_row0) * DDIM + ld_co0);
            cpasync16(smem_u32(&sZ[0][ld_row1][ld_co1]),
                      g_Zbf16 + (size_t)(tokenbase + ld_row1) * DDIM + ld_co1);
            cpasync16(smem_u32(&sE[0][ld_row0][ld_co0]),
                      g_Ebf16 + (size_t)(codebase + ld_row0) * DDIM + ld_co0);
            cpasync16(smem_u32(&sE[0][ld_row1][ld_co1]),
                      g_Ebf16 + (size_t)(codebase + ld_row1) * DDIM + ld_co1);
            cp_commit();
        }

        for (int s = 0; s < NSTAGE; s++) {
            int buf = s & 1;
            if (s + 1 < NSTAGE) {
                int nbuf = buf ^ 1;
                int ko = (s + 1) * BK;
                cpasync16(smem_u32(&sZ[nbuf][ld_row0][ld_co0]),
                          g_Zbf16 + (size_t)(tokenbase + ld_row0) * DDIM + ko + ld_co0);
                cpasync16(smem_u32(&sZ[nbuf][ld_row1][ld_co1]),
                          g_Zbf16 + (size_t)(tokenbase + ld_row1) * DDIM + ko + ld_co1);
                cpasync16(smem_u32(&sE[nbuf][ld_row0][ld_co0]),
                          g_Ebf16 + (size_t)(codebase + ld_row0) * DDIM + ko + ld_co0);
                cpasync16(smem_u32(&sE[nbuf][ld_row1][ld_co1]),
                          g_Ebf16 + (size_t)(codebase + ld_row1) * DDIM + ko + ld_co1);
                cp_commit();
                cp_wait<1>();
            } else {
                cp_wait<0>();
            }
            __syncthreads();

            uint32_t baseA = smem_u32(&sZ[buf][0][0]);
            uint32_t baseB = smem_u32(&sE[buf][0][0]);
            #pragma unroll
            for (int ks = 0; ks < BK / 16; ks++) {
                int kb = ks * 16;
                uint32_t afr[2][4];
                #pragma unroll
                for (int mf = 0; mf < 2; mf++) {
                    int mbase = wm * 32 + mf * 16;
                    uint32_t addr = baseA + (uint32_t)(((mbase + a_row_off) * SROWB + kb + a_col_off) * 2);
                    ldm4(afr[mf], addr);
                }
                #pragma unroll
                for (int nb = 0; nb < 4; nb++) {
                    int nbase = wn * 64 + nb * 16;
                    uint32_t bfr[4];
                    uint32_t addr = baseB + (uint32_t)(((nbase + b_row_off) * SROWB + kb + b_col_off) * 2);
                    ldm4(bfr, addr);
                    #pragma unroll
                    for (int mf = 0; mf < 2; mf++) {
                        mma16816(acc[mf][nb * 2 + 0], afr[mf], bfr[0], bfr[1]);
                        mma16816(acc[mf][nb * 2 + 1], afr[mf], bfr[2], bfr[3]);
                    }
                }
            }
            __syncthreads();  // all reads of buf done before it is refilled at s+2
        }

        // epilogue: running max + margin-guarded candidate append
        #pragma unroll
        for (int mf = 0; mf < 2; mf++) {
            #pragma unroll
            for (int half = 0; half < 2; half++) {
                int row = wm * 32 + mf * 16 + (lane >> 2) + half * 8;
                float v[16];
                #pragma unroll
                for (int nf = 0; nf < 8; nf++) {
                    v[2 * nf + 0] = acc[mf][nf][2 * half + 0];
                    v[2 * nf + 1] = acc[mf][nf][2 * half + 1];
                }
                float vmax = v[0];
                #pragma unroll
                for (int jv = 1; jv < 16; jv++) vmax = fmaxf(vmax, v[jv]);
                atomicMax(&smax[row], f2ord(vmax));
                float thr = ord2f(smax[row]) - MARGIN;
                int token = tokenbase + row;
                #pragma unroll
                for (int jv = 0; jv < 16; jv++) {
                    if (v[jv] > thr) {
                        int col = wn * 64 + (jv >> 1) * 8 + (lane & 3) * 2 + (jv & 1);
                        int code = codebase + col;
                        int p = atomicAdd(&g_cand_cnt[token], 1);
                        if (p < CAP) {
                            g_cand_code[token * CAP + p] = code;
                            g_cand_val[token * CAP + p] = v[jv];
                        }
                    }
                }
            }
        }
        __syncthreads();  // protect sZ/sE reuse vs stragglers in epilogue (paranoia, cheap)
    }

    if (tid < BM) atomicMax(&g_tokmax[tokenbase + tid], smax[tid]);
}

// ---------------- exact fp64 rescoring of candidates ----------------
__global__ void k_rescore() {
    int t = blockIdx.x;
    int tid = threadIdx.x;
    __shared__ double red[256];
    __shared__ double s_best;
    __shared__ int s_bidx;
    __shared__ double wval[8];
    __shared__ int widx[8];

    int raw = g_cand_cnt[t];
    float thr = ord2f(g_tokmax[t]) - MARGIN;
    if (tid == 0) { s_best = -1e300; s_bidx = KCODES; }
    __syncthreads();

    if (raw <= CAP) {
        for (int i = 0; i < raw; i++) {
            float v = g_cand_val[t * CAP + i];
            if (v < thr) continue;
            int code = g_cand_code[t * CAP + i];
            double s = 0.0;
            for (int c = tid; c < DDIM; c += 256)
                s += (double)g_Zf32[(size_t)t * DDIM + c] * (double)g_Ef32[(size_t)code * DDIM + c];
            red[tid] = s;
            __syncthreads();
            for (int off = 128; off > 0; off >>= 1) {
                if (tid < off) red[tid] += red[tid + off];
                __syncthreads();
            }
            if (tid == 0) {
                double tot = red[0];
                if (tot > s_best || (tot == s_best && code < s_bidx)) { s_best = tot; s_bidx = code; }
            }
            __syncthreads();
        }
    } else {
        // overflow fallback: exact full scan (practically never taken)
        int wp = tid >> 5, lane = tid & 31;
        double bw = -1e300; int bi = KCODES;
        for (int code = wp; code < KCODES; code += 8) {
            double s = 0.0;
            for (int c = lane; c < DDIM; c += 32)
                s += (double)g_Zf32[(size_t)t * DDIM + c] * (double)g_Ef32[(size_t)code * DDIM + c];
            #pragma unroll
            for (int off = 16; off > 0; off >>= 1) s += __shfl_down_sync(0xffffffffu, s, off);
            if (lane == 0) {
                if (s > bw || (s == bw && code < bi)) { bw = s; bi = code; }
            }
        }
        if (lane == 0) { wval[wp] = bw; widx[wp] = bi; }
        __syncthreads();
        if (tid == 0) {
            double bb = -1e300; int bix = KCODES;
            for (int wpi = 0; wpi < 8; wpi++) {
                if (wval[wpi] > bb || (wval[wpi] == bb && widx[wpi] < bix)) { bb = wval[wpi]; bix = widx[wpi]; }
            }
            s_best = bb; s_bidx = bix;
        }
        __syncthreads();
    }
    if (tid == 0) g_idx[t] = s_bidx;
}

// ---------------- gather quant output: out[b,c,h,w] = Ef32[idx[n]][c] ----------------
__global__ void k_output(float* __restrict__ out) {
    int bh = blockIdx.x;
    int b = bh >> 5, h = bh & 31;
    int n0 = bh * 32;
    int tid = threadIdx.x;
    __shared__ float st[64][33];
    __shared__ int rows[32];
    if (tid < 32) rows[tid] = g_idx[n0 + tid];
    __syncthreads();
    for (int cb = 0; cb < DDIM; cb += 64) {
        int w = tid >> 3, cc = tid & 7;
        int r = rows[w];
        #pragma unroll
        for (int i = 0; i < 8; i++)
            st[cc * 8 + i][w] = g_Ef32[(size_t)r * DDIM + cb + cc * 8 + i];
        __syncthreads();
        int c2 = tid >> 5, ww = tid & 31;
        #pragma unroll
        for (int kk = 0; kk < 8; kk++) {
            int c = c2 * 8 + kk;
            out[(((size_t)b * CCH + cb + c) * HH + h) * WW + ww] = st[c][ww];
        }
        __syncthreads();
    }
}

__global__ void k_idx_out(float* __restrict__ out) {
    int i = blockIdx.x * blockDim.x + threadIdx.x;
    if (i < NTOK) out[i] = (float)g_idx[i];
}

// ---------------- launch ----------------
extern "C" void kernel_launch(void* const* d_in, const int* in_sizes, int n_in,
                              void* d_out, int out_size) {
    const float* hid = (const float*)d_in[0];
    const float* emb = (const float*)d_in[1];
    // defensive: detect swapped input order by element counts
    if (n_in >= 2 && in_sizes[0] == KCODES * DDIM && in_sizes[1] == BB * CCH * HH * WW) {
        const float* t = hid; hid = emb; emb = t;
    }
    float* out = (float*)d_out;
    const int ND = NTOK * DDIM;  // 16777216

    k_init<<<(NTOK + 255) / 256, 256>>>();
    k_norm_embed<<<KCODES, 256>>>(emb);
    k_prep<<<BB * HH, 256>>>(hid);
    k_gemm<<<dim3(NTOK / BM, KPARTS), 256>>>();
    k_rescore<<<NTOK, 256>>>();

    if (out_size >= ND) {
        k_output<<<BB * HH, 256>>>(out);
        if (out_size >= ND + NTOK)
            k_idx_out<<<(NTOK + 255) / 256, 256>>>(out + (size_t)ND);
    } else if (out_size >= NTOK) {
        // idx-only output layout (defensive)
        k_idx_out<<<(NTOK + 255) / 256, 256>>>(out);
    }
}

// round 7
// speedup vs baseline: 1.1196x; 1.1196x over previous
#include <cuda_runtime.h>
#include <cuda_bf16.h>
#include <cstdint>

// Problem constants
#define KCODES 16384
#define DDIM   2048
#define NTOK   8192
#define BB 8
#define CCH 2048
#define HH 32
#define WW 32

// Candidate / GEMM config
#define CAP    256
#define KPARTS 8
#define BM 128
#define BN 128
#define BK 32
#define SROWB 40            // padded smem row: 80B; conflict-free for ldmatrix
#define NSTAGE (DDIM / BK)  // 64 k-stages
#define NBUF 3
#define MARGIN 3e-3f

// dynamic smem layout
#define STAGE_BYTES (BM * SROWB * 2)         // 10240 B per matrix per stage
#define SM_A_OFF 1024                        // [0,512): smax, pad to 1024
#define SM_B_OFF (SM_A_OFF + NBUF * STAGE_BYTES)
#define SM_TOTAL (SM_B_OFF + NBUF * STAGE_BYTES)   // 62464 B

// ---------------- scratch (device globals: no allocations allowed) ----------------
__device__ float          g_Ef32[(size_t)KCODES * DDIM];
__device__ __nv_bfloat16  g_Ebf16[(size_t)KCODES * DDIM];
__device__ float          g_Zf32[(size_t)NTOK * DDIM];
__device__ __nv_bfloat16  g_Zbf16[(size_t)NTOK * DDIM];
__device__ int            g_tokmax[NTOK];
__device__ int            g_cand_cnt[NTOK];
__device__ int            g_cand_code[NTOK * CAP];
__device__ float          g_cand_val[NTOK * CAP];
__device__ int            g_idx[NTOK];

// monotone float<->int ordering
__device__ __forceinline__ int f2ord(float f) {
    int i = __float_as_int(f);
    return (i >= 0) ? i : (i ^ 0x7fffffff);
}
__device__ __forceinline__ float ord2f(int i) {
    return __int_as_float((i >= 0) ? i : (i ^ 0x7fffffff));
}
__device__ __forceinline__ uint32_t smem_u32(const void* p) {
    return (uint32_t)__cvta_generic_to_shared(p);
}
__device__ __forceinline__ void ldm4(uint32_t r[4], uint32_t a) {
    asm volatile("ldmatrix.sync.aligned.m8n8.x4.shared.b16 {%0,%1,%2,%3}, [%4];"
                 : "=r"(r[0]), "=r"(r[1]), "=r"(r[2]), "=r"(r[3]) : "r"(a));
}
__device__ __forceinline__ void mma16816(float c[4], const uint32_t a[4], uint32_t b0, uint32_t b1) {
    asm volatile(
        "mma.sync.aligned.m16n8k16.row.col.f32.bf16.bf16.f32 "
        "{%0,%1,%2,%3},{%4,%5,%6,%7},{%8,%9},{%0,%1,%2,%3};"
        : "+f"(c[0]), "+f"(c[1]), "+f"(c[2]), "+f"(c[3])
        : "r"(a[0]), "r"(a[1]), "r"(a[2]), "r"(a[3]), "r"(b0), "r"(b1));
}
__device__ __forceinline__ void cpasync16(uint32_t saddr, const void* gaddr) {
    asm volatile("cp.async.cg.shared.global [%0], [%1], 16;" :: "r"(saddr), "l"(gaddr));
}
__device__ __forceinline__ void cp_commit() { asm volatile("cp.async.commit_group;"); }
template <int N>
__device__ __forceinline__ void cp_wait() { asm volatile("cp.async.wait_group %0;" :: "n"(N)); }

// ---------------- init per-launch state ----------------
__global__ void k_init() {
    int i = blockIdx.x * blockDim.x + threadIdx.x;
    if (i < NTOK) {
        g_cand_cnt[i] = 0;
        g_tokmax[i]  = 0x80000000;
    }
}

// ---------------- normalize embedding rows ----------------
__global__ void k_norm_embed(const float* __restrict__ emb) {
    int r = blockIdx.x;
    int tid = threadIdx.x;
    __shared__ float red[256];
    __shared__ float s_scale;
    const float4* src = (const float4*)(emb + (size_t)r * DDIM);
    float4 v0 = src[tid * 2 + 0];
    float4 v1 = src[tid * 2 + 1];
    float s = v0.x*v0.x + v0.y*v0.y + v0.z*v0.z + v0.w*v0.w
            + v1.x*v1.x + v1.y*v1.y + v1.z*v1.z + v1.w*v1.w;
    red[tid] = s;
    __syncthreads();
    for (int off = 128; off > 0; off >>= 1) {
        if (tid < off) red[tid] += red[tid + off];
        __syncthreads();
    }
    if (tid == 0) s_scale = 1.0f / fmaxf(sqrtf(red[0]), 1e-12f);
    __syncthreads();
    float sc = s_scale;
    float4 o0 = make_float4(v0.x*sc, v0.y*sc, v0.z*sc, v0.w*sc);
    float4 o1 = make_float4(v1.x*sc, v1.y*sc, v1.z*sc, v1.w*sc);
    ((float4*)(g_Ef32 + (size_t)r * DDIM))[tid * 2 + 0] = o0;
    ((float4*)(g_Ef32 + (size_t)r * DDIM))[tid * 2 + 1] = o1;
    __nv_bfloat16* db = g_Ebf16 + (size_t)r * DDIM + tid * 8;
    db[0] = __float2bfloat16_rn(o0.x); db[1] = __float2bfloat16_rn(o0.y);
    db[2] = __float2bfloat16_rn(o0.z); db[3] = __float2bfloat16_rn(o0.w);
    db[4] = __float2bfloat16_rn(o1.x); db[5] = __float2bfloat16_rn(o1.y);
    db[6] = __float2bfloat16_rn(o1.z); db[7] = __float2bfloat16_rn(o1.w);
}

// ---------------- transpose+normalize tokens: (B,C,H,W) -> [N,D] ----------------
__global__ void k_prep(const float* __restrict__ hid) {
    int bh = blockIdx.x;
    int b = bh >> 5, h = bh & 31;
    int n0 = bh * 32;
    int tid = threadIdx.x;
    int w = tid & 31, j = tid >> 5;
    __shared__ float red[8][32];
    __shared__ float invn[32];
    __shared__ float st[64][33];

    float ss = 0.0f;
    for (int c = j; c < DDIM; c += 8) {
        float v = hid[(((size_t)b * CCH + c) * HH + h) * WW + w];
        ss += v * v;
    }
    red[j][w] = ss;
    __syncthreads();
    if (tid < 32) {
        float t = 0.0f;
        #pragma unroll
        for (int jj = 0; jj < 8; jj++) t += red[jj][tid];
        invn[tid] = 1.0f / fmaxf(sqrtf(t), 1e-12f);
    }
    __syncthreads();

    for (int cb = 0; cb < DDIM; cb += 64) {
        float sc = invn[w];
        for (int r = j; r < 64; r += 8)
            st[r][w] = hid[(((size_t)b * CCH + cb + r) * HH + h) * WW + w] * sc;
        __syncthreads();
        int tok = tid >> 3, cc = tid & 7;
        size_t base = (size_t)(n0 + tok) * DDIM + cb;
        #pragma unroll
        for (int kk = 0; kk < 8; kk++) {
            int c = cc * 8 + kk;
            float v = st[c][tok];
            g_Zf32[base + c] = v;
            g_Zbf16[base + c] = __float2bfloat16_rn(v);
        }
        __syncthreads();
    }
}

// ---------------- stage loader: 2 A-chunks + 2 B-chunks (16B) per thread ----------------
__device__ __forceinline__ void load_stage(uint32_t smem_base, int tid,
                                           int tokenbase, int codebase, int s) {
    int buf = s % NBUF;
    int ko = s * BK;
    uint32_t aB = smem_base + SM_A_OFF + buf * STAGE_BYTES;
    uint32_t bB = smem_base + SM_B_OFF + buf * STAGE_BYTES;
    #pragma unroll
    for (int i = 0; i < 2; i++) {
        int chunk = i * 256 + tid;            // 0..511
        int row = chunk >> 2, cc = chunk & 3; // 4 x 16B chunks per 64B row-data
        uint32_t soff = (uint32_t)(row * (SROWB * 2) + cc * 16);
        cpasync16(aB + soff, g_Zbf16 + (size_t)(tokenbase + row) * DDIM + ko + cc * 8);
        cpasync16(bB + soff, g_Ebf16 + (size_t)(codebase + row) * DDIM + ko + cc * 8);
    }
}

// ---------------- bf16 HMMA GEMM, 3-stage cp.async ring, 1 barrier/stage ----------------
__global__ void __launch_bounds__(256, 2) k_gemm() {
    extern __shared__ __align__(1024) char dsm[];
    uint32_t smem_base = smem_u32(dsm);
    int* smax = (int*)dsm;

    int tid = threadIdx.x;
    int lane = tid & 31;
    int warp = tid >> 5;
    int wm = warp >> 1;     // 0..3, 32 rows each
    int wn = warp & 1;      // 0..1, 64 cols each

    int tokenbase = blockIdx.x * BM;
    int codebase0 = blockIdx.y * (KCODES / KPARTS);

    if (tid < BM) smax[tid] = 0x80000000;
    __syncthreads();

    // per-lane invariant smem read offsets (elements)
    int a_row_off = (lane & 15);
    int a_col_off = (lane >> 4) * 8;
    int b_row_off = (lane & 7) + ((lane >> 4) << 3);
    int b_col_off = ((lane >> 3) & 1) << 3;

    const int NT = (KCODES / KPARTS) / BN;  // 16 code tiles
    for (int ct = 0; ct < NT; ct++) {
        int codebase = codebase0 + ct * BN;
        float acc[2][8][4];
        #pragma unroll
        for (int a = 0; a < 2; a++)
            #pragma unroll
            for (int bfn = 0; bfn < 8; bfn++)
                #pragma unroll
                for (int q = 0; q < 4; q++) acc[a][bfn][q] = 0.0f;

        // prologue: stages 0 and 1 in flight
        load_stage(smem_base, tid, tokenbase, codebase, 0); cp_commit();
        load_stage(smem_base, tid, tokenbase, codebase, 1); cp_commit();

        for (int s = 0; s < NSTAGE; s++) {
            if (s + 2 < NSTAGE) cp_wait<1>(); else cp_wait<0>();
            __syncthreads();
            if (s + 2 < NSTAGE) {
                load_stage(smem_base, tid, tokenbase, codebase, s + 2);
                cp_commit();
            }

            int buf = s % NBUF;
            uint32_t baseA = smem_base + SM_A_OFF + buf * STAGE_BYTES;
            uint32_t baseB = smem_base + SM_B_OFF + buf * STAGE_BYTES;
            #pragma unroll
            for (int ks = 0; ks < BK / 16; ks++) {
                int kb = ks * 16;
                uint32_t afr[2][4];
                #pragma unroll
                for (int mf = 0; mf < 2; mf++) {
                    int mbase = wm * 32 + mf * 16;
                    uint32_t addr = baseA + (uint32_t)(((mbase + a_row_off) * SROWB + kb + a_col_off) * 2);
                    ldm4(afr[mf], addr);
                }
                #pragma unroll
                for (int nb = 0; nb < 4; nb++) {
                    int nbase = wn * 64 + nb * 16;
                    uint32_t bfr[4];
                    uint32_t addr = baseB + (uint32_t)(((nbase + b_row_off) * SROWB + kb + b_col_off) * 2);
                    ldm4(bfr, addr);
                    #pragma unroll
                    for (int mf = 0; mf < 2; mf++) {
                        mma16816(acc[mf][nb * 2 + 0], afr[mf], bfr[0], bfr[1]);
                        mma16816(acc[mf][nb * 2 + 1], afr[mf], bfr[2], bfr[3]);
                    }
                }
            }
        }

        // epilogue: running max + margin-guarded candidate append
        #pragma unroll
        for (int mf = 0; mf < 2; mf++) {
            #pragma unroll
            for (int half = 0; half < 2; half++) {
                int row = wm * 32 + mf * 16 + (lane >> 2) + half * 8;
                float v[16];
                #pragma unroll
                for (int nf = 0; nf < 8; nf++) {
                    v[2 * nf + 0] = acc[mf][nf][2 * half + 0];
                    v[2 * nf + 1] = acc[mf][nf][2 * half + 1];
                }
                float vmax = v[0];
                #pragma unroll
                for (int jv = 1; jv < 16; jv++) vmax = fmaxf(vmax, v[jv]);
                atomicMax(&smax[row], f2ord(vmax));
                float thr = ord2f(smax[row]) - MARGIN;
                int token = tokenbase + row;
                #pragma unroll
                for (int jv = 0; jv < 16; jv++) {
                    if (v[jv] > thr) {
                        int col = wn * 64 + (jv >> 1) * 8 + (lane & 3) * 2 + (jv & 1);
                        int code = codebase + col;
                        int p = atomicAdd(&g_cand_cnt[token], 1);
                        if (p < CAP) {
                            g_cand_code[token * CAP + p] = code;
                            g_cand_val[token * CAP + p] = v[jv];
                        }
                    }
                }
            }
        }
        __syncthreads();  // all lagging reads of last stage's buffer done before next tile's prologue
    }

    if (tid < BM) atomicMax(&g_tokmax[tokenbase + tid], smax[tid]);
}

// ---------------- exact fp64 rescoring of candidates ----------------
__global__ void k_rescore() {
    int t = blockIdx.x;
    int tid = threadIdx.x;
    __shared__ double red[256];
    __shared__ double s_best;
    __shared__ int s_bidx;
    __shared__ double wval[8];
    __shared__ int widx[8];

    int raw = g_cand_cnt[t];
    float thr = ord2f(g_tokmax[t]) - MARGIN;
    if (tid == 0) { s_best = -1e300; s_bidx = KCODES; }
    __syncthreads();

    if (raw <= CAP) {
        for (int i = 0; i < raw; i++) {
            float v = g_cand_val[t * CAP + i];
            if (v < thr) continue;
            int code = g_cand_code[t * CAP + i];
            double s = 0.0;
            for (int c = tid; c < DDIM; c += 256)
                s += (double)g_Zf32[(size_t)t * DDIM + c] * (double)g_Ef32[(size_t)code * DDIM + c];
            red[tid] = s;
            __syncthreads();
            for (int off = 128; off > 0; off >>= 1) {
                if (tid < off) red[tid] += red[tid + off];
                __syncthreads();
            }
            if (tid == 0) {
                double tot = red[0];
                if (tot > s_best || (tot == s_best && code < s_bidx)) { s_best = tot; s_bidx = code; }
            }
            __syncthreads();
        }
    } else {
        int wp = tid >> 5, lane = tid & 31;
        double bw = -1e300; int bi = KCODES;
        for (int code = wp; code < KCODES; code += 8) {
            double s = 0.0;
            for (int c = lane; c < DDIM; c += 32)
                s += (double)g_Zf32[(size_t)t * DDIM + c] * (double)g_Ef32[(size_t)code * DDIM + c];
            #pragma unroll
            for (int off = 16; off > 0; off >>= 1) s += __shfl_down_sync(0xffffffffu, s, off);
            if (lane == 0) {
                if (s > bw || (s == bw && code < bi)) { bw = s; bi = code; }
            }
        }
        if (lane == 0) { wval[wp] = bw; widx[wp] = bi; }
        __syncthreads();
        if (tid == 0) {
            double bb = -1e300; int bix = KCODES;
            for (int wpi = 0; wpi < 8; wpi++) {
                if (wval[wpi] > bb || (wval[wpi] == bb && widx[wpi] < bix)) { bb = wval[wpi]; bix = widx[wpi]; }
            }
            s_best = bb; s_bidx = bix;
        }
        __syncthreads();
    }
    if (tid == 0) g_idx[t] = s_bidx;
}

// ---------------- gather quant output ----------------
__global__ void k_output(float* __restrict__ out) {
    int bh = blockIdx.x;
    int b = bh >> 5, h = bh & 31;
    int n0 = bh * 32;
    int tid = threadIdx.x;
    __shared__ float st[64][33];
    __shared__ int rows[32];
    if (tid < 32) rows[tid] = g_idx[n0 + tid];
    __syncthreads();
    for (int cb = 0; cb < DDIM; cb += 64) {
        int w = tid >> 3, cc = tid & 7;
        int r = rows[w];
        #pragma unroll
        for (int i = 0; i < 8; i++)
            st[cc * 8 + i][w] = g_Ef32[(size_t)r * DDIM + cb + cc * 8 + i];
        __syncthreads();
        int c2 = tid >> 5, ww = tid & 31;
        #pragma unroll
        for (int kk = 0; kk < 8; kk++) {
            int c = c2 * 8 + kk;
            out[(((size_t)b * CCH + cb + c) * HH + h) * WW + ww] = st[c][ww];
        }
        __syncthreads();
    }
}

__global__ void k_idx_out(float* __restrict__ out) {
    int i = blockIdx.x * blockDim.x + threadIdx.x;
    if (i < NTOK) out[i] = (float)g_idx[i];
}

// ---------------- launch ----------------
extern "C" void kernel_launch(void* const* d_in, const int* in_sizes, int n_in,
                              void* d_out, int out_size) {
    const float* hid = (const float*)d_in[0];
    const float* emb = (const float*)d_in[1];
    if (n_in >= 2 && in_sizes[0] == KCODES * DDIM && in_sizes[1] == BB * CCH * HH * WW) {
        const float* t = hid; hid = emb; emb = t;
    }
    float* out = (float*)d_out;
    const int ND = NTOK * DDIM;

    cudaFuncSetAttribute(k_gemm, cudaFuncAttributeMaxDynamicSharedMemorySize, SM_TOTAL);

    k_init<<<(NTOK + 255) / 256, 256>>>();
    k_norm_embed<<<KCODES, 256>>>(emb);
    k_prep<<<BB * HH, 256>>>(hid);
    k_gemm<<<dim3(NTOK / BM, KPARTS), 256, SM_TOTAL>>>();
    k_rescore<<<NTOK, 256>>>();

    if (out_size >= ND) {
        k_output<<<BB * HH, 256>>>(out);
        if (out_size >= ND + NTOK)
            k_idx_out<<<(NTOK + 255) / 256, 256>>>(out + (size_t)ND);
    } else if (out_size >= NTOK) {
        k_idx_out<<<(NTOK + 255) / 256, 256>>>(out);
    }
}

// round 16
// speedup vs baseline: 1.2550x; 1.1209x over previous
#include <cuda_runtime.h>
#include <cuda_bf16.h>
#include <cstdint>

// Problem constants
#define KCODES 16384
#define DDIM   2048
#define NTOK   8192
#define BB 8
#define CCH 2048
#define HH 32
#define WW 32

// Candidate / GEMM config
#define CAP    256
#define KPARTS 8
#define BM 128
#define BN 128
#define BK 64
#define SROWB 72            // padded smem row: 144B; rows stride 9x16B -> conflict-free ldmatrix
#define NSTAGE (DDIM / BK)  // 32 k-stages
#define NBUF 2
#define MARGIN 3e-3f

// dynamic smem layout
#define STAGE_BYTES (BM * SROWB * 2)         // 18432 B per matrix per stage
#define SM_A_OFF 1024                        // [0,512): smax, pad to 1024
#define SM_B_OFF (SM_A_OFF + NBUF * STAGE_BYTES)
#define SM_TOTAL (SM_B_OFF + NBUF * STAGE_BYTES)   // 74752 B

// ---------------- scratch (device globals: no allocations allowed) ----------------
__device__ float          g_Ef32[(size_t)KCODES * DDIM];
__device__ __nv_bfloat16  g_Ebf16[(size_t)KCODES * DDIM];
__device__ float          g_Zf32[(size_t)NTOK * DDIM];
__device__ __nv_bfloat16  g_Zbf16[(size_t)NTOK * DDIM];
__device__ int            g_tokmax[NTOK];
__device__ int            g_cand_cnt[NTOK];
__device__ int            g_cand_code[NTOK * CAP];
__device__ float          g_cand_val[NTOK * CAP];
__device__ int            g_idx[NTOK];

// monotone float<->int ordering
__device__ __forceinline__ int f2ord(float f) {
    int i = __float_as_int(f);
    return (i >= 0) ? i : (i ^ 0x7fffffff);
}
__device__ __forceinline__ float ord2f(int i) {
    return __int_as_float((i >= 0) ? i : (i ^ 0x7fffffff));
}
__device__ __forceinline__ uint32_t smem_u32(const void* p) {
    return (uint32_t)__cvta_generic_to_shared(p);
}
__device__ __forceinline__ void ldm4(uint32_t r[4], uint32_t a) {
    asm volatile("ldmatrix.sync.aligned.m8n8.x4.shared.b16 {%0,%1,%2,%3}, [%4];"
                 : "=r"(r[0]), "=r"(r[1]), "=r"(r[2]), "=r"(r[3]) : "r"(a));
}
__device__ __forceinline__ void mma16816(float c[4], const uint32_t a[4], uint32_t b0, uint32_t b1) {
    asm volatile(
        "mma.sync.aligned.m16n8k16.row.col.f32.bf16.bf16.f32 "
        "{%0,%1,%2,%3},{%4,%5,%6,%7},{%8,%9},{%0,%1,%2,%3};"
        : "+f"(c[0]), "+f"(c[1]), "+f"(c[2]), "+f"(c[3])
        : "r"(a[0]), "r"(a[1]), "r"(a[2]), "r"(a[3]), "r"(b0), "r"(b1));
}
__device__ __forceinline__ void cpasync16(uint32_t saddr, const void* gaddr) {
    asm volatile("cp.async.cg.shared.global [%0], [%1], 16;" :: "r"(saddr), "l"(gaddr));
}
__device__ __forceinline__ void cp_commit() { asm volatile("cp.async.commit_group;"); }
template <int N>
__device__ __forceinline__ void cp_wait() { asm volatile("cp.async.wait_group %0;" :: "n"(N)); }

// ---------------- normalize embedding rows ----------------
__global__ void k_norm_embed(const float* __restrict__ emb) {
    int r = blockIdx.x;
    int tid = threadIdx.x;
    __shared__ float red[256];
    __shared__ float s_scale;
    const float4* src = (const float4*)(emb + (size_t)r * DDIM);
    float4 v0 = src[tid * 2 + 0];
    float4 v1 = src[tid * 2 + 1];
    float s = v0.x*v0.x + v0.y*v0.y + v0.z*v0.z + v0.w*v0.w
            + v1.x*v1.x + v1.y*v1.y + v1.z*v1.z + v1.w*v1.w;
    red[tid] = s;
    __syncthreads();
    for (int off = 128; off > 0; off >>= 1) {
        if (tid < off) red[tid] += red[tid + off];
        __syncthreads();
    }
    if (tid == 0) s_scale = 1.0f / fmaxf(sqrtf(red[0]), 1e-12f);
    __syncthreads();
    float sc = s_scale;
    float4 o0 = make_float4(v0.x*sc, v0.y*sc, v0.z*sc, v0.w*sc);
    float4 o1 = make_float4(v1.x*sc, v1.y*sc, v1.z*sc, v1.w*sc);
    ((float4*)(g_Ef32 + (size_t)r * DDIM))[tid * 2 + 0] = o0;
    ((float4*)(g_Ef32 + (size_t)r * DDIM))[tid * 2 + 1] = o1;
    __nv_bfloat16* db = g_Ebf16 + (size_t)r * DDIM + tid * 8;
    db[0] = __float2bfloat16_rn(o0.x); db[1] = __float2bfloat16_rn(o0.y);
    db[2] = __float2bfloat16_rn(o0.z); db[3] = __float2bfloat16_rn(o0.w);
    db[4] = __float2bfloat16_rn(o1.x); db[5] = __float2bfloat16_rn(o1.y);
    db[6] = __float2bfloat16_rn(o1.z); db[7] = __float2bfloat16_rn(o1.w);
}

// ---------------- transpose+normalize tokens: (B,C,H,W) -> [N,D] + per-token init ----------------
__global__ void k_prep(const float* __restrict__ hid) {
    int bh = blockIdx.x;
    int b = bh >> 5, h = bh & 31;
    int n0 = bh * 32;
    int tid = threadIdx.x;
    int w = tid & 31, j = tid >> 5;
    __shared__ float red[8][32];
    __shared__ float invn[32];
    __shared__ float st[64][33];

    // fused per-token candidate-state init (this block owns tokens n0..n0+31)
    if (tid < 32) {
        g_cand_cnt[n0 + tid] = 0;
        g_tokmax[n0 + tid] = 0x80000000;
    }

    float ss = 0.0f;
    for (int c = j; c < DDIM; c += 8) {
        float v = hid[(((size_t)b * CCH + c) * HH + h) * WW + w];
        ss += v * v;
    }
    red[j][w] = ss;
    __syncthreads();
    if (tid < 32) {
        float t = 0.0f;
        #pragma unroll
        for (int jj = 0; jj < 8; jj++) t += red[jj][tid];
        invn[tid] = 1.0f / fmaxf(sqrtf(t), 1e-12f);
    }
    __syncthreads();

    for (int cb = 0; cb < DDIM; cb += 64) {
        float sc = invn[w];
        for (int r = j; r < 64; r += 8)
            st[r][w] = hid[(((size_t)b * CCH + cb + r) * HH + h) * WW + w] * sc;
        __syncthreads();
        int tok = tid >> 3, cc = tid & 7;
        size_t base = (size_t)(n0 + tok) * DDIM + cb;
        #pragma unroll
        for (int kk = 0; kk < 8; kk++) {
            int c = cc * 8 + kk;
            float v = st[c][tok];
            g_Zf32[base + c] = v;
            g_Zbf16[base + c] = __float2bfloat16_rn(v);
        }
        __syncthreads();
    }
}

// ---------------- stage loader: 4 A-chunks + 4 B-chunks (16B) per thread ----------------
__device__ __forceinline__ void load_stage(uint32_t smem_base, int tid,
                                           int tokenbase, int codebase, int s) {
    int buf = s & 1;
    int ko = s * BK;
    uint32_t aB = smem_base + SM_A_OFF + buf * STAGE_BYTES;
    uint32_t bB = smem_base + SM_B_OFF + buf * STAGE_BYTES;
    #pragma unroll
    for (int i = 0; i < 4; i++) {
        int chunk = i * 256 + tid;            // 0..1023
        int row = chunk >> 3, cc = chunk & 7; // 8 x 16B chunks per 128B row-data
        uint32_t soff = (uint32_t)(row * (SROWB * 2) + cc * 16);
        cpasync16(aB + soff, g_Zbf16 + (size_t)(tokenbase + row) * DDIM + ko + cc * 8);
        cpasync16(bB + soff, g_Ebf16 + (size_t)(codebase + row) * DDIM + ko + cc * 8);
    }
}

// ---------------- bf16 HMMA GEMM, BK=64, 2-buffer ring, 1 barrier/stage ----------------
__global__ void __launch_bounds__(256, 2) k_gemm() {
    extern __shared__ __align__(1024) char dsm[];
    uint32_t smem_base = smem_u32(dsm);
    int* smax = (int*)dsm;

    int tid = threadIdx.x;
    int lane = tid & 31;
    int warp = tid >> 5;
    int wm = warp >> 1;     // 0..3, 32 rows each
    int wn = warp & 1;      // 0..1, 64 cols each

    int tokenbase = blockIdx.x * BM;
    int codebase0 = blockIdx.y * (KCODES / KPARTS);

    if (tid < BM) smax[tid] = 0x80000000;
    __syncthreads();

    // per-lane invariant smem read offsets (elements)
    int a_row_off = (lane & 15);
    int a_col_off = (lane >> 4) * 8;
    int b_row_off = (lane & 7) + ((lane >> 4) << 3);
    int b_col_off = ((lane >> 3) & 1) << 3;

    const int NT = (KCODES / KPARTS) / BN;  // 16 code tiles
    for (int ct = 0; ct < NT; ct++) {
        int codebase = codebase0 + ct * BN;
        float acc[2][8][4];
        #pragma unroll
        for (int a = 0; a < 2; a++)
            #pragma unroll
            for (int bfn = 0; bfn < 8; bfn++)
                #pragma unroll
                for (int q = 0; q < 4; q++) acc[a][bfn][q] = 0.0f;

        // prologue: stage 0 in flight
        load_stage(smem_base, tid, tokenbase, codebase, 0);
        cp_commit();

        for (int s = 0; s < NSTAGE; s++) {
            cp_wait<0>();        // group(s) landed (issued a full stage ago, cheap)
            __syncthreads();     // all warps done reading buffer being overwritten next
            if (s + 1 < NSTAGE) {
                load_stage(smem_base, tid, tokenbase, codebase, s + 1);
                cp_commit();
            }

            int buf = s & 1;
            uint32_t baseA = smem_base + SM_A_OFF + buf * STAGE_BYTES;
            uint32_t baseB = smem_base + SM_B_OFF + buf * STAGE_BYTES;
            #pragma unroll
            for (int ks = 0; ks < BK / 16; ks++) {
                int kb = ks * 16;
                // load ALL fragments first (hide LDS latency behind LDSM issue train)
                uint32_t afr[2][4];
                #pragma unroll
                for (int mf = 0; mf < 2; mf++) {
                    int mbase = wm * 32 + mf * 16;
                    uint32_t addr = baseA + (uint32_t)(((mbase + a_row_off) * SROWB + kb + a_col_off) * 2);
                    ldm4(afr[mf], addr);
                }
                uint32_t bfr[4][4];
                #pragma unroll
                for (int nb = 0; nb < 4; nb++) {
                    int nbase = wn * 64 + nb * 16;
                    uint32_t addr = baseB + (uint32_t)(((nbase + b_row_off) * SROWB + kb + b_col_off) * 2);
                    ldm4(bfr[nb], addr);
                }
                // then all 16 MMAs
                #pragma unroll
                for (int nb = 0; nb < 4; nb++) {
                    #pragma unroll
                    for (int mf = 0; mf < 2; mf++) {
                        mma16816(acc[mf][nb * 2 + 0], afr[mf], bfr[nb][0], bfr[nb][1]);
                        mma16816(acc[mf][nb * 2 + 1], afr[mf], bfr[nb][2], bfr[nb][3]);
                    }
                }
            }
        }

        // epilogue: running max + margin-guarded candidate append
        #pragma unroll
        for (int mf = 0; mf < 2; mf++) {
            #pragma unroll
            for (int half = 0; half < 2; half++) {
                int row = wm * 32 + mf * 16 + (lane >> 2) + half * 8;
                float v[16];
                #pragma unroll
                for (int nf = 0; nf < 8; nf++) {
                    v[2 * nf + 0] = acc[mf][nf][2 * half + 0];
                    v[2 * nf + 1] = acc[mf][nf][2 * half + 1];
                }
                float vmax = v[0];
                #pragma unroll
                for (int jv = 1; jv < 16; jv++) vmax = fmaxf(vmax, v[jv]);
                atomicMax(&smax[row], f2ord(vmax));
                float thr = ord2f(smax[row]) - MARGIN;
                int token = tokenbase + row;
                #pragma unroll
                for (int jv = 0; jv < 16; jv++) {
                    if (v[jv] > thr) {
                        int col = wn * 64 + (jv >> 1) * 8 + (lane & 3) * 2 + (jv & 1);
                        int code = codebase + col;
                        int p = atomicAdd(&g_cand_cnt[token], 1);
                        if (p < CAP) {
                            g_cand_code[token * CAP + p] = code;
                            g_cand_val[token * CAP + p] = v[jv];
                        }
                    }
                }
            }
        }
        __syncthreads();  // smax atomics + lagging buffer reads quiesce before next tile
    }

    if (tid < BM) atomicMax(&g_tokmax[tokenbase + tid], smax[tid]);
}

// ---------------- exact fp64 rescoring of candidates ----------------
__global__ void k_rescore() {
    int t = blockIdx.x;
    int tid = threadIdx.x;
    __shared__ double red[256];
    __shared__ double s_best;
    __shared__ int s_bidx;
    __shared__ double wval[8];
    __shared__ int widx[8];

    int raw = g_cand_cnt[t];
    float thr = ord2f(g_tokmax[t]) - MARGIN;
    if (tid == 0) { s_best = -1e300; s_bidx = KCODES; }
    __syncthreads();

    if (raw <= CAP) {
        for (int i = 0; i < raw; i++) {
            float v = g_cand_val[t * CAP + i];
            if (v < thr) continue;
            int code = g_cand_code[t * CAP + i];
            double s = 0.0;
            for (int c = tid; c < DDIM; c += 256)
                s += (double)g_Zf32[(size_t)t * DDIM + c] * (double)g_Ef32[(size_t)code * DDIM + c];
            red[tid] = s;
            __syncthreads();
            for (int off = 128; off > 0; off >>= 1) {
                if (tid < off) red[tid] += red[tid + off];
                __syncthreads();
            }
            if (tid == 0) {
                double tot = red[0];
                if (tot > s_best || (tot == s_best && code < s_bidx)) { s_best = tot; s_bidx = code; }
            }
            __syncthreads();
        }
    } else {
        int wp = tid >> 5, lane = tid & 31;
        double bw = -1e300; int bi = KCODES;
        for (int code = wp; code < KCODES; code += 8) {
            double s = 0.0;
            for (int c = lane; c < DDIM; c += 32)
                s += (double)g_Zf32[(size_t)t * DDIM + c] * (double)g_Ef32[(size_t)code * DDIM + c];
            #pragma unroll
            for (int off = 16; off > 0; off >>= 1) s += __shfl_down_sync(0xffffffffu, s, off);
            if (lane == 0) {
                if (s > bw || (s == bw && code < bi)) { bw = s; bi = code; }
            }
        }
        if (lane == 0) { wval[wp] = bw; widx[wp] = bi; }
        __syncthreads();
        if (tid == 0) {
            double bb = -1e300; int bix = KCODES;
            for (int wpi = 0; wpi < 8; wpi++) {
                if (wval[wpi] > bb || (wval[wpi] == bb && widx[wpi] < bix)) { bb = wval[wpi]; bix = widx[wpi]; }
            }
            s_best = bb; s_bidx = bix;
        }
        __syncthreads();
    }
    if (tid == 0) g_idx[t] = s_bidx;
}

// ---------------- gather quant output ----------------
__global__ void k_output(float* __restrict__ out) {
    int bh = blockIdx.x;
    int b = bh >> 5, h = bh & 31;
    int n0 = bh * 32;
    int tid = threadIdx.x;
    __shared__ float st[64][33];
    __shared__ int rows[32];
    if (tid < 32) rows[tid] = g_idx[n0 + tid];
    __syncthreads();
    for (int cb = 0; cb < DDIM; cb += 64) {
        int w = tid >> 3, cc = tid & 7;
        int r = rows[w];
        #pragma unroll
        for (int i = 0; i < 8; i++)
            st[cc * 8 + i][w] = g_Ef32[(size_t)r * DDIM + cb + cc * 8 + i];
        __syncthreads();
        int c2 = tid >> 5, ww = tid & 31;
        #pragma unroll
        for (int kk = 0; kk < 8; kk++) {
            int c = c2 * 8 + kk;
            out[(((size_t)b * CCH + cb + c) * HH + h) * WW + ww] = st[c][ww];
        }
        __syncthreads();
    }
}

__global__ void k_idx_out(float* __restrict__ out) {
    int i = blockIdx.x * blockDim.x + threadIdx.x;
    if (i < NTOK) out[i] = (float)g_idx[i];
}

// ---------------- launch ----------------
extern "C" void kernel_launch(void* const* d_in, const int* in_sizes, int n_in,
                              void* d_out, int out_size) {
    const float* hid = (const float*)d_in[0];
    const float* emb = (const float*)d_in[1];
    if (n_in >= 2 && in_sizes[0] == KCODES * DDIM && in_sizes[1] == BB * CCH * HH * WW) {
        const float* t = hid; hid = emb; emb = t;
    }
    float* out = (float*)d_out;
    const int ND = NTOK * DDIM;

    cudaFuncSetAttribute(k_gemm, cudaFuncAttributeMaxDynamicSharedMemorySize, SM_TOTAL);

    k_norm_embed<<<KCODES, 256>>>(emb);
    k_prep<<<BB * HH, 256>>>(hid);
    k_gemm<<<dim3(NTOK / BM, KPARTS), 256, SM_TOTAL>>>();
    k_rescore<<<NTOK, 256>>>();

    if (out_size >= ND) {
        k_output<<<BB * HH, 256>>>(out);
        if (out_size >= ND + NTOK)
            k_idx_out<<<(NTOK + 255) / 256, 256>>>(out + (size_t)ND);
    } else if (out_size >= NTOK) {
        k_idx_out<<<(NTOK + 255) / 256, 256>>>(out);
    }
}